// round 5
// baseline (speedup 1.0000x reference)
#include <cuda_runtime.h>
#include <cstdint>

namespace {
constexpr int NS    = 512;
constexpr int MPTS  = 8192;
constexpr int HW4   = 4096;          // float4 words per 128x128 plane
constexpr int GRID  = 740;           // 148 SMs x 5 resident blocks = one wave
constexpr int BLOCK = 256;
constexpr int PVC   = 8;             // pv chunks per sample (512 f4 = 2048 px)
constexpr int MSC   = 4;             // mesh chunks per sample (2048 pts)
constexpr int PV_F4 = HW4 / PVC;     // 512
constexpr int MS_PT = MPTS / MSC;    // 2048
constexpr unsigned NC = (unsigned)NS * (PVC + MSC);   // 6144 chunks, 12 per sample
}

__device__ float2   g_pv[NS * PVC];    // (sum, cnt) partials
__device__ float2   g_ms[NS * MSC];    // (ad, pj) partials
__device__ unsigned g_cnt[NS];         // zero-init; self-resetting per launch

__device__ __forceinline__ float frcp(float x)  { float r; asm("rcp.approx.f32 %0,%1;"  : "=f"(r) : "f"(x)); return r; }
__device__ __forceinline__ float fsqrt(float x) { float r; asm("sqrt.approx.f32 %0,%1;" : "=f"(r) : "f"(x)); return r; }

__global__ void __launch_bounds__(BLOCK, 5) score_kernel(
    const int*   __restrict__ obj_id,
    const float* __restrict__ camK,
    const float* __restrict__ Rg_all,
    const float* __restrict__ tg_all,
    const float* __restrict__ Rp_all,
    const float* __restrict__ tp_all,
    const float* __restrict__ coord,
    const void*  __restrict__ mask,
    const float* __restrict__ mesh,
    const float* __restrict__ diam,
    float*       __restrict__ out)     // [5*NS]: re|te|ad|pj|pv
{
    const int tid  = threadIdx.x;
    const int lane = tid & 31;
    const int wid  = tid >> 5;

    __shared__ float2 sred[8];
    __shared__ int    smode;

    // ---- mask dtype detection (warp 0, first 512B): 0=f32, 1=i32, 2=packed u8 ----
    if (wid == 0) {
        const unsigned* mw = (const unsigned*)mask;
        unsigned f = 0, o = 0;
#pragma unroll
        for (int k = 0; k < 4; k++) {
            unsigned w = __ldg(mw + lane + 32 * k);
            if (w == 0x3F800000u) f = 1;
            else if (w > 1u) o = 1;
        }
        f = __any_sync(0xFFFFFFFFu, f);
        o = __any_sync(0xFFFFFFFFu, o);
        if (lane == 0) smode = f ? 0 : (o ? 2 : 1);
    }
    __syncthreads();
    const int mode = smode;

    // ---- persistent chunk loop: interleaved 2 pv : 1 mesh ----
    for (unsigned c = blockIdx.x; c < NC; c += GRID) {
        const unsigned grp = c / 3u;
        const unsigned rem = c - grp * 3u;
        const bool ispv = (rem < 2u);

        float r0 = 0.f, r1 = 0.f;
        int n, sidx;

        if (ispv) {
            // ============ PV chunk: 2048 ROI pixels (512 float4) ============
            const int p = (int)(grp * 2u + rem);
            n = p >> 3;
            const int part = p & 7;
            sidx = p;

            float Rp[9], Rg[9];
#pragma unroll
            for (int i = 0; i < 9; i++) {
                Rp[i] = __ldg(Rp_all + n * 9 + i);
                Rg[i] = __ldg(Rg_all + n * 9 + i);
            }
            const float tp0 = __ldg(tp_all + n*3+0), tp1 = __ldg(tp_all + n*3+1), tp2 = __ldg(tp_all + n*3+2);
            const float tg0 = __ldg(tg_all + n*3+0), tg1 = __ldg(tg_all + n*3+1), tg2 = __ldg(tg_all + n*3+2);
            const float fx  = __ldg(camK + n*9 + 0), fy = __ldg(camK + n*9 + 4);

            const float4* c4 = (const float4*)coord + (size_t)n * 3 * HW4 + part * PV_F4;
            const size_t mbase = (size_t)n * HW4 + (size_t)part * PV_F4;

#pragma unroll
            for (int it = 0; it < PV_F4 / BLOCK; ++it) {
                const int f = it * BLOCK + tid;
                float4 X = c4[f], Y = c4[f + HW4], Z = c4[f + 2 * HW4];
                float mv[4];
                if (mode == 0) {
                    float4 M = ((const float4*)mask)[mbase + f];
                    mv[0] = M.x; mv[1] = M.y; mv[2] = M.z; mv[3] = M.w;
                } else if (mode == 1) {
                    int4 M = ((const int4*)mask)[mbase + f];
                    mv[0] = (float)M.x; mv[1] = (float)M.y; mv[2] = (float)M.z; mv[3] = (float)M.w;
                } else {
                    unsigned w = ((const unsigned*)mask)[mbase + f];
                    mv[0] = (float)(w & 255u);         mv[1] = (float)((w >> 8) & 255u);
                    mv[2] = (float)((w >> 16) & 255u); mv[3] = (float)(w >> 24);
                }
                const float xs[4] = {X.x, X.y, X.z, X.w};
                const float ys[4] = {Y.x, Y.y, Y.z, Y.w};
                const float zs[4] = {Z.x, Z.y, Z.z, Z.w};
#pragma unroll
                for (int k = 0; k < 4; k++) {
                    const float v0 = xs[k], v1 = ys[k], v2 = zs[k];
                    float p0 = fmaf(Rp[0], v0, fmaf(Rp[1], v1, fmaf(Rp[2], v2, tp0)));
                    float p1 = fmaf(Rp[3], v0, fmaf(Rp[4], v1, fmaf(Rp[5], v2, tp1)));
                    float p2 = fmaf(Rp[6], v0, fmaf(Rp[7], v1, fmaf(Rp[8], v2, tp2)));
                    float g0 = fmaf(Rg[0], v0, fmaf(Rg[1], v1, fmaf(Rg[2], v2, tg0)));
                    float g1 = fmaf(Rg[3], v0, fmaf(Rg[4], v1, fmaf(Rg[5], v2, tg1)));
                    float g2 = fmaf(Rg[6], v0, fmaf(Rg[7], v1, fmaf(Rg[8], v2, tg2)));
                    // p0/p2 - g0/g2 = (p0*g2 - g0*p2)/(p2*g2): one MUFU rcp
                    float t0 = fmaf(p0, g2, -(g0 * p2));
                    float t1 = fmaf(p1, g2, -(g1 * p2));
                    float r  = frcp(p2 * g2);
                    float du = fx * (t0 * r);
                    float dv = fy * (t1 * r);
                    float d  = fsqrt(fmaf(du, du, dv * dv));
                    r0 = fmaf(d, mv[k], r0);
                    r1 += mv[k];
                }
            }
        } else {
            // ============ MESH chunk: 2048 points (4 pts per 3 float4) ============
            const int m = (int)grp;
            n = m >> 2;
            const int part = m & 3;
            sidx = m;

            const int obj = __ldg(obj_id + n);
            float Rg[9], dR[9];
#pragma unroll
            for (int i = 0; i < 9; i++) {
                Rg[i] = __ldg(Rg_all + n * 9 + i);
                dR[i] = __ldg(Rp_all + n * 9 + i) - Rg[i];
            }
            const float tg0 = __ldg(tg_all + n*3+0), tg1 = __ldg(tg_all + n*3+1), tg2 = __ldg(tg_all + n*3+2);
            const float dt0 = __ldg(tp_all + n*3+0) - tg0;
            const float dt1 = __ldg(tp_all + n*3+1) - tg1;
            const float dt2 = __ldg(tp_all + n*3+2) - tg2;
            const float fx  = __ldg(camK + n*9 + 0), fy = __ldg(camK + n*9 + 4);

            // 4 points = 3 float4 per thread-group step
            const float4* m4 = (const float4*)mesh + (size_t)obj * (MPTS * 3 / 4)
                                                   + (size_t)part * (MS_PT * 3 / 4);
#pragma unroll
            for (int g = 0; g < MS_PT / (BLOCK * 4); ++g) {
                const int base3 = (g * BLOCK + tid) * 3;
                float4 A = __ldg(m4 + base3);
                float4 B = __ldg(m4 + base3 + 1);
                float4 C = __ldg(m4 + base3 + 2);
                const float px[4] = {A.x, A.w, B.z, C.y};
                const float py[4] = {A.y, B.x, B.w, C.z};
                const float pz[4] = {A.z, B.y, C.x, C.w};
#pragma unroll
                for (int k = 0; k < 4; k++) {
                    const float v0 = px[k], v1 = py[k], v2 = pz[k];
                    float e0 = fmaf(dR[0], v0, fmaf(dR[1], v1, fmaf(dR[2], v2, dt0)));
                    float e1 = fmaf(dR[3], v0, fmaf(dR[4], v1, fmaf(dR[5], v2, dt1)));
                    float e2 = fmaf(dR[6], v0, fmaf(dR[7], v1, fmaf(dR[8], v2, dt2)));
                    float g0 = fmaf(Rg[0], v0, fmaf(Rg[1], v1, fmaf(Rg[2], v2, tg0)));
                    float g1 = fmaf(Rg[3], v0, fmaf(Rg[4], v1, fmaf(Rg[5], v2, tg1)));
                    float g2 = fmaf(Rg[6], v0, fmaf(Rg[7], v1, fmaf(Rg[8], v2, tg2)));
                    r0 += fsqrt(fmaf(e0, e0, fmaf(e1, e1, e2 * e2)));
                    // p = g + e; p0/p2 - g0/g2 = (e0*g2 - g0*e2)/(p2*g2)
                    float t0 = fmaf(e0, g2, -(g0 * e2));
                    float t1 = fmaf(e1, g2, -(g1 * e2));
                    float p2 = g2 + e2;
                    float r  = frcp(p2 * g2);
                    float du = fx * (t0 * r);
                    float dv = fy * (t1 * r);
                    r1 += fsqrt(fmaf(du, du, dv * dv));
                }
            }
        }

        // ---- block reduction (8 warps) ----
#pragma unroll
        for (int s = 16; s; s >>= 1) {
            r0 += __shfl_down_sync(0xFFFFFFFFu, r0, s);
            r1 += __shfl_down_sync(0xFFFFFFFFu, r1, s);
        }
        if (lane == 0) sred[wid] = make_float2(r0, r1);
        __syncthreads();

        if (tid == 0) {
            float s0 = 0.f, s1 = 0.f;
#pragma unroll
            for (int k = 0; k < 8; k++) { s0 += sred[k].x; s1 += sred[k].y; }
            if (ispv) g_pv[sidx] = make_float2(s0, s1);
            else      g_ms[sidx] = make_float2(s0, s1);
            __threadfence();
            unsigned old = atomicAdd(&g_cnt[n], 1u);
            if (old == (unsigned)(PVC + MSC - 1)) {
                // ---- finisher: all 12 partials of sample n are in ----
                __threadfence();
                float pvs = 0.f, pvc = 0.f, ads = 0.f, pjs = 0.f;
#pragma unroll
                for (int k = 0; k < PVC; k++) {
                    float2 v = __ldcg(&g_pv[n * PVC + k]); pvs += v.x; pvc += v.y;
                }
#pragma unroll
                for (int k = 0; k < MSC; k++) {
                    float2 v = __ldcg(&g_ms[n * MSC + k]); ads += v.x; pjs += v.y;
                }
                out[4 * NS + n] = pvs / fmaxf(pvc, 1.0f);
                const int ob = __ldg(obj_id + n);
                out[2 * NS + n] = ads * (1.0f / MPTS) / __ldg(diam + ob);
                out[3 * NS + n] = pjs * (1.0f / MPTS);
                // RE / TE (reload consts; rare path)
                float tr = 0.f;
#pragma unroll
                for (int i = 0; i < 9; i++)
                    tr = fmaf(__ldg(Rp_all + n * 9 + i), __ldg(Rg_all + n * 9 + i), tr);
                tr = fminf(fmaxf(tr, -1.0f), 3.0f);
                out[n] = acosf((tr - 1.0f) * 0.5f) * 57.29577951308232f;
                float d0 = __ldg(tp_all + n*3+0) - __ldg(tg_all + n*3+0);
                float d1 = __ldg(tp_all + n*3+1) - __ldg(tg_all + n*3+1);
                float d2 = __ldg(tp_all + n*3+2) - __ldg(tg_all + n*3+2);
                out[NS + n] = sqrtf(fmaf(d0, d0, fmaf(d1, d1, d2 * d2))) * 100.0f;
                g_cnt[n] = 0u;   // self-reset for next graph replay
            }
        }
        __syncthreads();
    }
}

extern "C" void kernel_launch(void* const* d_in, const int* in_sizes, int n_in,
                              void* d_out, int out_size) {
    (void)in_sizes; (void)n_in; (void)out_size;
    const int*   obj_id = (const int*)  d_in[0];
    const float* camK   = (const float*)d_in[1];
    const float* gtR    = (const float*)d_in[2];
    const float* gtT    = (const float*)d_in[3];
    const float* prR    = (const float*)d_in[4];
    const float* prT    = (const float*)d_in[5];
    const float* coord  = (const float*)d_in[6];
    const void*  mask   =               d_in[7];
    const float* mesh   = (const float*)d_in[8];
    const float* diam   = (const float*)d_in[9];
    float* out = (float*)d_out;

    score_kernel<<<GRID, BLOCK>>>(obj_id, camK, gtR, gtT, prR, prT,
                                  coord, mask, mesh, diam, out);
}